// round 3
// baseline (speedup 1.0000x reference)
#include <cuda_runtime.h>
#include <math.h>

#define CELLS_PER_BLOCK 256
#define SLOTS 15
#define FLOATS_PER_BLOCK (CELLS_PER_BLOCK * SLOTS)          // 3840 floats = 15360 B (16B aligned)
#define VEC4_PER_BLOCK   (FLOATS_PER_BLOCK / 4)             // 960 float4
#define EPSF 1e-9f

// Device-global scratch (zero-initialized at module load; self-reset by the
// last block each run so graph replays stay deterministic).
__device__ double g_loss_accum = 0.0;
__device__ unsigned int g_blocks_done = 0;

__global__ __launch_bounds__(CELLS_PER_BLOCK)
void yolo_loss_fused_kernel(const float* __restrict__ o,
                            const float* __restrict__ t,
                            float* __restrict__ out,
                            int nblocks) {
    __shared__ float so[FLOATS_PER_BLOCK];
    __shared__ float st[FLOATS_PER_BLOCK];
    __shared__ float warp_part[CELLS_PER_BLOCK / 32];
    __shared__ bool is_last;

    const int tid = threadIdx.x;
    const long long base = (long long)blockIdx.x * FLOATS_PER_BLOCK;

    // Coalesced staging: 960 float4 per tensor; streaming loads (read-once data)
    const float4* o4 = reinterpret_cast<const float4*>(o + base);
    const float4* t4 = reinterpret_cast<const float4*>(t + base);
    float4* so4 = reinterpret_cast<float4*>(so);
    float4* st4 = reinterpret_cast<float4*>(st);

#pragma unroll
    for (int i = 0; i < 4; i++) {
        int idx = tid + i * CELLS_PER_BLOCK;
        if (idx < VEC4_PER_BLOCK) {
            so4[idx] = __ldcs(&o4[idx]);
            st4[idx] = __ldcs(&t4[idx]);
        }
    }
    __syncthreads();

    // One thread per cell; stride-15 smem reads are bank-conflict-free
    const float* co = so + tid * SLOTS;
    const float* ct = st + tid * SLOTS;

    float loss = 0.0f;
    const float o0 = co[0];
    if (o0 != 0.0f) {
        // coordinate loss: x + sqrt(w) + sqrt(h) terms
        float d0 = o0 - ct[0];
        float dw = sqrtf(co[2]) - sqrtf(ct[2]);
        float dh = sqrtf(co[3]) - sqrtf(ct[3]);
        float coord = d0 * d0 + dw * dw + dh * dh;

        // BCE on confidence slot
        float tc = ct[4];
        float oc = co[4];
        float conf = -(tc * logf(oc + EPSF) + (1.0f - tc) * logf(1.0f - oc + EPSF));

        // class loss over slots 5..13
        float cls = 0.0f;
#pragma unroll
        for (int k = 5; k < 14; k++) {
            float d = ct[k] - co[k];
            cls = fmaf(d, d, cls);
        }
        loss = coord + conf + cls;
    }

    // warp reduce
#pragma unroll
    for (int off = 16; off > 0; off >>= 1)
        loss += __shfl_xor_sync(0xFFFFFFFFu, loss, off);

    const int wid = tid >> 5;
    const int lid = tid & 31;
    if (lid == 0) warp_part[wid] = loss;
    __syncthreads();

    if (wid == 0) {
        float v = (lid < (CELLS_PER_BLOCK / 32)) ? warp_part[lid] : 0.0f;
#pragma unroll
        for (int off = 4; off > 0; off >>= 1)
            v += __shfl_xor_sync(0xFFFFFFFFu, v, off);

        if (lid == 0) {
            atomicAdd(&g_loss_accum, (double)v);
            __threadfence();
            unsigned int done = atomicInc(&g_blocks_done, (unsigned int)(nblocks - 1));
            is_last = (done == (unsigned int)(nblocks - 1));
        }
    }
    __syncthreads();

    // Last block finalizes: write output and reset scratch for next replay
    if (is_last && tid == 0) {
        __threadfence();
        out[0] = (float)g_loss_accum;
        g_loss_accum = 0.0;
        // g_blocks_done already wrapped to 0 by atomicInc's modulus
    }
}

extern "C" void kernel_launch(void* const* d_in, const int* in_sizes, int n_in,
                              void* d_out, int out_size) {
    const float* o = (const float*)d_in[0];
    const float* t = (const float*)d_in[1];
    float* out = (float*)d_out;

    const long long total_floats = (long long)in_sizes[0];     // 512 * 47040
    const long long total_cells = total_floats / SLOTS;        // 1,605,632
    const int nblocks = (int)((total_cells + CELLS_PER_BLOCK - 1) / CELLS_PER_BLOCK); // 6272

    yolo_loss_fused_kernel<<<nblocks, CELLS_PER_BLOCK>>>(o, t, out, nblocks);
}

// round 4
// speedup vs baseline: 1.0101x; 1.0101x over previous
#include <cuda_runtime.h>
#include <math.h>
#include <stdint.h>

#define THREADS 256
#define SLOTS 15
#define CELLS_PER_TILE 256
#define FLOATS_PER_TILE (CELLS_PER_TILE * SLOTS)     // 3840 floats = 15360 B
#define VEC4_PER_TILE (FLOATS_PER_TILE / 4)          // 960
#define TILES_PER_BLOCK 4
#define STAGE_FLOATS (2 * FLOATS_PER_TILE)           // o + t per stage
#define SMEM_BYTES (2 * STAGE_FLOATS * 4)            // 61440 B (double buffer)
#define EPSF 1e-9f

__device__ double g_loss_accum = 0.0;
__device__ unsigned int g_blocks_done = 0;

__device__ __forceinline__ uint32_t smem_u32(const void* p) {
    return (uint32_t)__cvta_generic_to_shared(p);
}
__device__ __forceinline__ void cp16(uint32_t s, const void* g) {
    asm volatile("cp.async.cg.shared.global [%0], [%1], 16;\n" :: "r"(s), "l"(g));
}

__global__ __launch_bounds__(THREADS)
void yolo_loss_pipe_kernel(const float* __restrict__ o,
                           const float* __restrict__ t,
                           float* __restrict__ out,
                           int total_tiles, int nblocks) {
    extern __shared__ float smem[];          // [2 stages][o tile | t tile]
    __shared__ float warp_part[THREADS / 32];
    __shared__ bool is_last;

    const int tid = threadIdx.x;
    const int tile0 = blockIdx.x * TILES_PER_BLOCK;

    // ---- prefetch helper (issues up to 8 cp.async + commit) ----
    auto prefetch = [&](int it, int stage) {
        int tile = tile0 + it;
        if (tile >= total_tiles) { asm volatile("cp.async.commit_group;\n"); return; }
        long long base = (long long)tile * FLOATS_PER_TILE;
        const float4* o4 = reinterpret_cast<const float4*>(o + base);
        const float4* t4 = reinterpret_cast<const float4*>(t + base);
        float* so = smem + stage * STAGE_FLOATS;
        float* st = so + FLOATS_PER_TILE;
#pragma unroll
        for (int i = 0; i < 4; i++) {
            int idx = tid + i * THREADS;
            if (idx < VEC4_PER_TILE) {
                cp16(smem_u32(so + idx * 4), o4 + idx);
                cp16(smem_u32(st + idx * 4), t4 + idx);
            }
        }
        asm volatile("cp.async.commit_group;\n");
    };

    prefetch(0, 0);

    float acc = 0.0f;

#pragma unroll
    for (int it = 0; it < TILES_PER_BLOCK; it++) {
        if (it + 1 < TILES_PER_BLOCK) {
            prefetch(it + 1, (it + 1) & 1);
            asm volatile("cp.async.wait_group 1;\n");
        } else {
            asm volatile("cp.async.wait_group 0;\n");
        }
        __syncthreads();

        if (tile0 + it < total_tiles) {
            const float* so = smem + (it & 1) * STAGE_FLOATS;
            const float* st = so + FLOATS_PER_TILE;
            const float* co = so + tid * SLOTS;   // stride-15: conflict-free
            const float* ct = st + tid * SLOTS;

            const float o0 = co[0];
            if (o0 != 0.0f) {
                float d0 = o0 - ct[0];
                float dw = sqrtf(co[2]) - sqrtf(ct[2]);
                float dh = sqrtf(co[3]) - sqrtf(ct[3]);
                float loss = d0 * d0 + dw * dw + dh * dh;

                float tc = ct[4];
                float oc = co[4];
                loss -= tc * logf(oc + EPSF) + (1.0f - tc) * logf(1.0f - oc + EPSF);

#pragma unroll
                for (int k = 5; k < 14; k++) {
                    float d = ct[k] - co[k];
                    loss = fmaf(d, d, loss);
                }
                acc += loss;
            }
        }
        __syncthreads();   // buffer safe for reuse by next-next prefetch
    }

    // ---- block reduction ----
#pragma unroll
    for (int off = 16; off > 0; off >>= 1)
        acc += __shfl_xor_sync(0xFFFFFFFFu, acc, off);

    const int wid = tid >> 5;
    const int lid = tid & 31;
    if (lid == 0) warp_part[wid] = acc;
    __syncthreads();

    if (wid == 0) {
        float v = (lid < (THREADS / 32)) ? warp_part[lid] : 0.0f;
#pragma unroll
        for (int off = 4; off > 0; off >>= 1)
            v += __shfl_xor_sync(0xFFFFFFFFu, v, off);

        if (lid == 0) {
            atomicAdd(&g_loss_accum, (double)v);
            __threadfence();
            unsigned int done = atomicInc(&g_blocks_done, (unsigned int)(nblocks - 1));
            is_last = (done == (unsigned int)(nblocks - 1));
        }
    }
    __syncthreads();

    if (is_last && tid == 0) {
        __threadfence();
        out[0] = (float)g_loss_accum;
        g_loss_accum = 0.0;   // self-reset for graph replay determinism
    }
}

extern "C" void kernel_launch(void* const* d_in, const int* in_sizes, int n_in,
                              void* d_out, int out_size) {
    const float* o = (const float*)d_in[0];
    const float* t = (const float*)d_in[1];
    float* out = (float*)d_out;

    const long long total_floats = (long long)in_sizes[0];   // 512 * 47040
    const long long total_cells = total_floats / SLOTS;      // 1,605,632
    const int total_tiles = (int)((total_cells + CELLS_PER_TILE - 1) / CELLS_PER_TILE); // 6272
    const int nblocks = (total_tiles + TILES_PER_BLOCK - 1) / TILES_PER_BLOCK;          // 1568

    static bool attr_done = false;
    cudaFuncSetAttribute(yolo_loss_pipe_kernel,
                         cudaFuncAttributeMaxDynamicSharedMemorySize, SMEM_BYTES);
    (void)attr_done;

    yolo_loss_pipe_kernel<<<nblocks, THREADS, SMEM_BYTES>>>(o, t, out, total_tiles, nblocks);
}

// round 5
// speedup vs baseline: 1.1509x; 1.1395x over previous
#include <cuda_runtime.h>
#include <math.h>
#include <stdint.h>

#define THREADS 256
#define SLOTS 15
#define CELLS_PER_TILE 256
#define TILE_FLOATS (CELLS_PER_TILE * SLOTS)      // 3840 floats
#define TILE_BYTES  (TILE_FLOATS * 4)             // 15360 B (16B aligned)
#define STAGES 3
#define STAGE_FLOATS (2 * TILE_FLOATS)            // o tile + t tile
#define STAGE_BYTES  (2 * TILE_BYTES)             // 30720 B
#define SMEM_BYTES   (STAGES * STAGE_BYTES)       // 92160 B -> 2 CTAs/SM
#define GRID_CTAS 296                             // 2 per SM on 148 SMs
#define EPSF 1e-9f

__device__ double g_loss_accum = 0.0;
__device__ unsigned int g_blocks_done = 0;

__device__ __forceinline__ uint32_t smem_u32(const void* p) {
    return (uint32_t)__cvta_generic_to_shared(p);
}
__device__ __forceinline__ void mbar_init(uint32_t mbar, uint32_t count) {
    asm volatile("mbarrier.init.shared.b64 [%0], %1;" :: "r"(mbar), "r"(count) : "memory");
}
__device__ __forceinline__ void mbar_expect_tx(uint32_t mbar, uint32_t bytes) {
    asm volatile("mbarrier.arrive.expect_tx.shared.b64 _, [%0], %1;" :: "r"(mbar), "r"(bytes) : "memory");
}
__device__ __forceinline__ void mbar_wait(uint32_t mbar, uint32_t parity) {
    uint32_t done;
    asm volatile(
        "{\n\t.reg .pred p;\n\t"
        "mbarrier.try_wait.parity.acquire.cta.shared::cta.b64 p, [%1], %2;\n\t"
        "selp.b32 %0, 1, 0, p;\n\t}"
        : "=r"(done) : "r"(mbar), "r"(parity) : "memory");
    if (!done) {
        asm volatile(
            "{\n\t.reg .pred P1;\n\t"
            "WAIT_LOOP_%=:\n\t"
            "mbarrier.try_wait.parity.acquire.cta.shared::cta.b64 P1, [%0], %1, 0x989680;\n\t"
            "@P1 bra.uni WAIT_DONE_%=;\n\t"
            "bra.uni WAIT_LOOP_%=;\n\t"
            "WAIT_DONE_%=:\n\t}"
            :: "r"(mbar), "r"(parity) : "memory");
    }
}
__device__ __forceinline__ void bulk_cp(uint32_t smem_dst, const void* gmem_src,
                                        uint32_t bytes, uint32_t mbar) {
    asm volatile(
        "cp.async.bulk.shared::cluster.global.mbarrier::complete_tx::bytes [%0], [%1], %2, [%3];"
        :: "r"(smem_dst), "l"(gmem_src), "r"(bytes), "r"(mbar) : "memory");
}

__global__ __launch_bounds__(THREADS)
void yolo_loss_tma_kernel(const float* __restrict__ o,
                          const float* __restrict__ t,
                          float* __restrict__ out,
                          int total_tiles, int nblocks) {
    extern __shared__ float smem[];                 // STAGES x [o tile | t tile]
    __shared__ uint64_t full_bar[STAGES];
    __shared__ float warp_part[THREADS / 32];
    __shared__ bool is_last;

    const int tid = threadIdx.x;
    const int bid = blockIdx.x;

    // Contiguous tile partition: first `rem` blocks get q+1 tiles
    const int q = total_tiles / nblocks;
    const int rem = total_tiles - q * nblocks;
    const int my_n = q + (bid < rem ? 1 : 0);
    const int my_start = bid * q + (bid < rem ? bid : rem);

    if (tid == 0) {
        for (int s = 0; s < STAGES; s++)
            mbar_init(smem_u32(&full_bar[s]), 1);
        asm volatile("fence.proxy.async.shared::cta;" ::: "memory");
    }
    __syncthreads();

    // Prologue: fill all stages
    if (tid == 0) {
        int pre = my_n < STAGES ? my_n : STAGES;
        for (int j = 0; j < pre; j++) {
            long long base = (long long)(my_start + j) * TILE_FLOATS;
            uint32_t so = smem_u32(smem + j * STAGE_FLOATS);
            uint32_t mb = smem_u32(&full_bar[j]);
            mbar_expect_tx(mb, STAGE_BYTES);
            bulk_cp(so, o + base, TILE_BYTES, mb);
            bulk_cp(so + TILE_BYTES, t + base, TILE_BYTES, mb);
        }
    }

    float acc = 0.0f;

    for (int k = 0; k < my_n; k++) {
        const int stage = k % STAGES;
        const uint32_t parity = (uint32_t)((k / STAGES) & 1);

        mbar_wait(smem_u32(&full_bar[stage]), parity);

        const float* so = smem + stage * STAGE_FLOATS;
        const float* st = so + TILE_FLOATS;
        const float* co = so + tid * SLOTS;         // stride-15: bank-conflict-free
        const float* ct = st + tid * SLOTS;

        const float o0 = co[0];
        if (o0 != 0.0f) {
            float d0 = o0 - ct[0];
            float dw = sqrtf(co[2]) - sqrtf(ct[2]);
            float dh = sqrtf(co[3]) - sqrtf(ct[3]);
            float loss = d0 * d0 + dw * dw + dh * dh;

            float tc = ct[4];
            float oc = co[4];
            loss -= tc * logf(oc + EPSF) + (1.0f - tc) * logf(1.0f - oc + EPSF);

#pragma unroll
            for (int s = 5; s < 14; s++) {
                float d = ct[s] - co[s];
                loss = fmaf(d, d, loss);
            }
            acc += loss;
        }

        __syncthreads();   // all threads done reading stage -> safe to refill

        if (tid == 0 && (k + STAGES) < my_n) {
            long long base = (long long)(my_start + k + STAGES) * TILE_FLOATS;
            uint32_t so_dst = smem_u32(smem + stage * STAGE_FLOATS);
            uint32_t mb = smem_u32(&full_bar[stage]);
            mbar_expect_tx(mb, STAGE_BYTES);
            bulk_cp(so_dst, o + base, TILE_BYTES, mb);
            bulk_cp(so_dst + TILE_BYTES, t + base, TILE_BYTES, mb);
        }
    }

    // ---- block reduction ----
#pragma unroll
    for (int off = 16; off > 0; off >>= 1)
        acc += __shfl_xor_sync(0xFFFFFFFFu, acc, off);

    const int wid = tid >> 5;
    const int lid = tid & 31;
    if (lid == 0) warp_part[wid] = acc;
    __syncthreads();

    if (wid == 0) {
        float v = (lid < (THREADS / 32)) ? warp_part[lid] : 0.0f;
#pragma unroll
        for (int off = 4; off > 0; off >>= 1)
            v += __shfl_xor_sync(0xFFFFFFFFu, v, off);

        if (lid == 0) {
            atomicAdd(&g_loss_accum, (double)v);
            __threadfence();
            unsigned int done = atomicInc(&g_blocks_done, (unsigned int)(nblocks - 1));
            is_last = (done == (unsigned int)(nblocks - 1));
        }
    }
    __syncthreads();

    if (is_last && tid == 0) {
        __threadfence();
        out[0] = (float)g_loss_accum;
        g_loss_accum = 0.0;    // self-reset for graph replay determinism
    }
}

extern "C" void kernel_launch(void* const* d_in, const int* in_sizes, int n_in,
                              void* d_out, int out_size) {
    const float* o = (const float*)d_in[0];
    const float* t = (const float*)d_in[1];
    float* out = (float*)d_out;

    const long long total_floats = (long long)in_sizes[0];    // 512 * 47040
    const long long total_cells = total_floats / SLOTS;       // 1,605,632
    const int total_tiles = (int)(total_cells / CELLS_PER_TILE); // 6272 (exact)

    int nblocks = GRID_CTAS;
    if (nblocks > total_tiles) nblocks = total_tiles;

    cudaFuncSetAttribute(yolo_loss_tma_kernel,
                         cudaFuncAttributeMaxDynamicSharedMemorySize, SMEM_BYTES);

    yolo_loss_tma_kernel<<<nblocks, THREADS, SMEM_BYTES>>>(o, t, out, total_tiles, nblocks);
}

// round 6
// speedup vs baseline: 1.1963x; 1.0394x over previous
#include <cuda_runtime.h>
#include <math.h>
#include <stdint.h>

#define THREADS 256
#define SLOTS 15
#define CELLS_PER_TILE 256
#define TILE_FLOATS (CELLS_PER_TILE * SLOTS)      // 3840 floats
#define TILE_BYTES  (TILE_FLOATS * 4)             // 15360 B (16B aligned)
#define STAGES 3
#define STAGE_FLOATS (2 * TILE_FLOATS)            // o tile + t tile
#define STAGE_BYTES  (2 * TILE_BYTES)             // 30720 B
#define SMEM_BYTES   (STAGES * STAGE_BYTES)       // 92160 B -> 2 CTAs/SM
#define GRID_CTAS 296                             // 2 per SM on 148 SMs
#define EPSF 1e-9f
#define LN2F 0.6931471805599453f

__device__ double g_loss_accum = 0.0;
__device__ unsigned int g_blocks_done = 0;

__device__ __forceinline__ uint32_t smem_u32(const void* p) {
    return (uint32_t)__cvta_generic_to_shared(p);
}
__device__ __forceinline__ void mbar_init(uint32_t mbar, uint32_t count) {
    asm volatile("mbarrier.init.shared.b64 [%0], %1;" :: "r"(mbar), "r"(count) : "memory");
}
__device__ __forceinline__ void mbar_expect_tx(uint32_t mbar, uint32_t bytes) {
    asm volatile("mbarrier.arrive.expect_tx.shared.b64 _, [%0], %1;" :: "r"(mbar), "r"(bytes) : "memory");
}
__device__ __forceinline__ void mbar_wait(uint32_t mbar, uint32_t parity) {
    uint32_t done;
    asm volatile(
        "{\n\t.reg .pred p;\n\t"
        "mbarrier.try_wait.parity.acquire.cta.shared::cta.b64 p, [%1], %2;\n\t"
        "selp.b32 %0, 1, 0, p;\n\t}"
        : "=r"(done) : "r"(mbar), "r"(parity) : "memory");
    if (!done) {
        asm volatile(
            "{\n\t.reg .pred P1;\n\t"
            "WAIT_LOOP_%=:\n\t"
            "mbarrier.try_wait.parity.acquire.cta.shared::cta.b64 P1, [%0], %1, 0x989680;\n\t"
            "@P1 bra.uni WAIT_DONE_%=;\n\t"
            "bra.uni WAIT_LOOP_%=;\n\t"
            "WAIT_DONE_%=:\n\t}"
            :: "r"(mbar), "r"(parity) : "memory");
    }
}
__device__ __forceinline__ void bulk_cp(uint32_t smem_dst, const void* gmem_src,
                                        uint32_t bytes, uint32_t mbar) {
    asm volatile(
        "cp.async.bulk.shared::cluster.global.mbarrier::complete_tx::bytes [%0], [%1], %2, [%3];"
        :: "r"(smem_dst), "l"(gmem_src), "r"(bytes), "r"(mbar) : "memory");
}
__device__ __forceinline__ float fast_sqrt(float x) {
    float r; asm("sqrt.approx.f32 %0, %1;" : "=f"(r) : "f"(x)); return r;
}
__device__ __forceinline__ float fast_lg2(float x) {
    float r; asm("lg2.approx.f32 %0, %1;" : "=f"(r) : "f"(x)); return r;
}

__global__ __launch_bounds__(THREADS)
void yolo_loss_tma_kernel(const float* __restrict__ o,
                          const float* __restrict__ t,
                          float* __restrict__ out,
                          int total_tiles, int nblocks) {
    extern __shared__ float smem[];                 // STAGES x [o tile | t tile]
    __shared__ uint64_t full_bar[STAGES];
    __shared__ float warp_part[THREADS / 32];
    __shared__ bool is_last;

    const int tid = threadIdx.x;
    const int bid = blockIdx.x;

    const int q = total_tiles / nblocks;
    const int rem = total_tiles - q * nblocks;
    const int my_n = q + (bid < rem ? 1 : 0);
    const int my_start = bid * q + (bid < rem ? bid : rem);

    if (tid == 0) {
        for (int s = 0; s < STAGES; s++)
            mbar_init(smem_u32(&full_bar[s]), 1);
        asm volatile("fence.proxy.async.shared::cta;" ::: "memory");
    }
    __syncthreads();

    // Prologue: fill all stages
    if (tid == 0) {
        int pre = my_n < STAGES ? my_n : STAGES;
        for (int j = 0; j < pre; j++) {
            long long base = (long long)(my_start + j) * TILE_FLOATS;
            uint32_t so = smem_u32(smem + j * STAGE_FLOATS);
            uint32_t mb = smem_u32(&full_bar[j]);
            mbar_expect_tx(mb, STAGE_BYTES);
            bulk_cp(so, o + base, TILE_BYTES, mb);
            bulk_cp(so + TILE_BYTES, t + base, TILE_BYTES, mb);
        }
    }

    float acc = 0.0f;

    for (int k = 0; k < my_n; k++) {
        const int stage = k % STAGES;
        const uint32_t parity = (uint32_t)((k / STAGES) & 1);

        mbar_wait(smem_u32(&full_bar[stage]), parity);

        const float* so = smem + stage * STAGE_FLOATS;
        const float* st = so + TILE_FLOATS;
        const float* co = so + tid * SLOTS;         // stride-15: bank-conflict-free
        const float* ct = st + tid * SLOTS;

        const float o0 = co[0];

        // coord: (o0-t0)^2 + (sqrt(o2)-sqrt(t2))^2 + (sqrt(o3)-sqrt(t3))^2
        //  using (sqrt(a)-sqrt(b))^2 = a + b - 2*sqrt(a*b)
        float d0 = o0 - ct[0];
        float ow = co[2], tw = ct[2];
        float oh = co[3], th = ct[3];
        float loss = d0 * d0 + ow + tw + oh + th
                   - 2.0f * (fast_sqrt(ow * tw) + fast_sqrt(oh * th));

        // BCE: -( t4*ln(o4+e) + (1-t4)*ln(1-o4+e) ) via lg2.approx
        float tc = ct[4];
        float oc = co[4];
        float l_pos = fast_lg2(oc + EPSF);
        float l_neg = fast_lg2(1.0f - oc + EPSF);
        loss -= LN2F * (tc * (l_pos - l_neg) + l_neg);

        // class loss over slots 5..13
#pragma unroll
        for (int s = 5; s < 14; s++) {
            float d = ct[s] - co[s];
            loss = fmaf(d, d, loss);
        }

        acc += (o0 != 0.0f) ? loss : 0.0f;

        __syncthreads();   // all threads done reading stage -> safe to refill

        if (tid == 0 && (k + STAGES) < my_n) {
            long long base = (long long)(my_start + k + STAGES) * TILE_FLOATS;
            uint32_t so_dst = smem_u32(smem + stage * STAGE_FLOATS);
            uint32_t mb = smem_u32(&full_bar[stage]);
            mbar_expect_tx(mb, STAGE_BYTES);
            bulk_cp(so_dst, o + base, TILE_BYTES, mb);
            bulk_cp(so_dst + TILE_BYTES, t + base, TILE_BYTES, mb);
        }
    }

    // ---- block reduction ----
#pragma unroll
    for (int off = 16; off > 0; off >>= 1)
        acc += __shfl_xor_sync(0xFFFFFFFFu, acc, off);

    const int wid = tid >> 5;
    const int lid = tid & 31;
    if (lid == 0) warp_part[wid] = acc;
    __syncthreads();

    if (wid == 0) {
        float v = (lid < (THREADS / 32)) ? warp_part[lid] : 0.0f;
#pragma unroll
        for (int off = 4; off > 0; off >>= 1)
            v += __shfl_xor_sync(0xFFFFFFFFu, v, off);

        if (lid == 0) {
            atomicAdd(&g_loss_accum, (double)v);
            __threadfence();
            unsigned int done = atomicInc(&g_blocks_done, (unsigned int)(nblocks - 1));
            is_last = (done == (unsigned int)(nblocks - 1));
        }
    }
    __syncthreads();

    if (is_last && tid == 0) {
        __threadfence();
        out[0] = (float)g_loss_accum;
        g_loss_accum = 0.0;    // self-reset for graph replay determinism
    }
}

extern "C" void kernel_launch(void* const* d_in, const int* in_sizes, int n_in,
                              void* d_out, int out_size) {
    const float* o = (const float*)d_in[0];
    const float* t = (const float*)d_in[1];
    float* out = (float*)d_out;

    const long long total_floats = (long long)in_sizes[0];       // 512 * 47040
    const long long total_cells = total_floats / SLOTS;          // 1,605,632
    const int total_tiles = (int)(total_cells / CELLS_PER_TILE); // 6272 (exact)

    int nblocks = GRID_CTAS;
    if (nblocks > total_tiles) nblocks = total_tiles;

    cudaFuncSetAttribute(yolo_loss_tma_kernel,
                         cudaFuncAttributeMaxDynamicSharedMemorySize, SMEM_BYTES);

    yolo_loss_tma_kernel<<<nblocks, THREADS, SMEM_BYTES>>>(o, t, out, total_tiles, nblocks);
}